// round 10
// baseline (speedup 1.0000x reference)
#include <cuda_runtime.h>
#include <cuda_fp16.h>
#include <cstddef>

#define DIM 128
#define MAX_GROUPS 50000
#define MAX_USERS  200000
#define MAX_NNZ    2000000

#define H_SCALE   0.0009765625f   // 2^-10 (exact)
#define H_UNSCALE 1024.0f         // 2^10  (exact)

// ---------------------------------------------------------------------------
// Scratch (device globals; no allocation allowed)
// ---------------------------------------------------------------------------
__device__ float g_node_msg[(size_t)MAX_GROUPS * DIM];
__device__ __half g_userh[(size_t)MAX_USERS * DIM];          // fp16 user operand (scaled 2^-10)
__device__ __half g_msgh[3][(size_t)MAX_GROUPS * DIM];       // fp16 msg slots (scaled 2^-10)

__device__ int  g_cntA[MAX_GROUPS];
__device__ int  g_ptrA[MAX_GROUPS + 1];
__device__ int  g_workA[MAX_GROUPS];
__device__ int  g_bsumA[256];
__device__ int2 g_ivA[MAX_NNZ];          // CSR by group row: (user_col, val)

__device__ int  g_cntB[MAX_USERS];
__device__ int  g_ptrB[MAX_USERS + 1];
__device__ int  g_workB[MAX_USERS];
__device__ int  g_bsumB[256];
__device__ int2 g_ivB[MAX_NNZ];          // CSC by user col: (group_row, val)

// ---------------------------------------------------------------------------
// f32x2 packed-math helpers (Blackwell FFMA2 via PTX)
// ---------------------------------------------------------------------------
__device__ __forceinline__ unsigned long long pack2(float lo, float hi)
{
    unsigned long long r;
    asm("mov.b64 %0, {%1, %2};" : "=l"(r) : "f"(lo), "f"(hi));
    return r;
}
__device__ __forceinline__ void ffma2(unsigned long long& d,
                                      unsigned long long a, unsigned long long b)
{
    asm("fma.rn.f32x2 %0, %1, %2, %0;" : "+l"(d) : "l"(a), "l"(b));
}
__device__ __forceinline__ float2 unpack2(unsigned long long v)
{
    float2 r;
    asm("mov.b64 {%0, %1}, %2;" : "=f"(r.x), "=f"(r.y) : "l"(v));
    return r;
}

// unpack 4 halfs -> float4
__device__ __forceinline__ float4 unpack_h4(unsigned lo, unsigned hi)
{
    __half2 h0 = *reinterpret_cast<__half2*>(&lo);
    __half2 h1 = *reinterpret_cast<__half2*>(&hi);
    float2 a = __half22float2(h0);
    float2 b = __half22float2(h1);
    return make_float4(a.x, a.y, b.x, b.y);
}
// pack float4 -> 4 halfs (uint2)
__device__ __forceinline__ uint2 pack_h4(float4 v)
{
    __half2 h0 = __floats2half2_rn(v.x, v.y);
    __half2 h1 = __floats2half2_rn(v.z, v.w);
    uint2 r;
    r.x = *reinterpret_cast<unsigned*>(&h0);
    r.y = *reinterpret_cast<unsigned*>(&h1);
    return r;
}

// ---------------------------------------------------------------------------
// fp32 -> scaled fp16 (x * 2^-10, exact scaling)
__global__ void f32_to_f16_kernel(const float4* __restrict__ in, uint2* __restrict__ out, int n4)
{
    int i = blockIdx.x * blockDim.x + threadIdx.x;
    if (i < n4) {
        float4 v = in[i];
        v.x *= H_SCALE; v.y *= H_SCALE; v.z *= H_SCALE; v.w *= H_SCALE;
        out[i] = pack_h4(v);
    }
}

// ---------------------------------------------------------------------------
// CSR build: histogram -> 3-pass exclusive scan -> scatter
// ---------------------------------------------------------------------------
__global__ void hist_kernel(const int* __restrict__ rows, const int* __restrict__ cols,
                            int* __restrict__ cntA, int* __restrict__ cntB, int nnz)
{
    int i = blockIdx.x * blockDim.x + threadIdx.x;
    if (i < nnz) {
        atomicAdd(cntA + rows[i], 1);
        atomicAdd(cntB + cols[i], 1);
    }
}

__global__ void scan_block_kernel(const int* __restrict__ cnt, int* __restrict__ out,
                                  int* __restrict__ bsums, int n)
{
    __shared__ int sm[1024];
    int i = blockIdx.x * 1024 + threadIdx.x;
    int v = (i < n) ? cnt[i] : 0;
    sm[threadIdx.x] = v;
    __syncthreads();
    for (int off = 1; off < 1024; off <<= 1) {
        int t = (threadIdx.x >= off) ? sm[threadIdx.x - off] : 0;
        __syncthreads();
        sm[threadIdx.x] += t;
        __syncthreads();
    }
    if (i < n) out[i] = sm[threadIdx.x];
    if (threadIdx.x == 1023) bsums[blockIdx.x] = sm[1023];
}

__global__ void scan_small_kernel(int* __restrict__ bsums, int nb)
{
    __shared__ int sm[256];
    int v = (threadIdx.x < nb) ? bsums[threadIdx.x] : 0;
    sm[threadIdx.x] = v;
    __syncthreads();
    for (int off = 1; off < 256; off <<= 1) {
        int t = (threadIdx.x >= off) ? sm[threadIdx.x - off] : 0;
        __syncthreads();
        sm[threadIdx.x] += t;
        __syncthreads();
    }
    if (threadIdx.x < nb)
        bsums[threadIdx.x] = (threadIdx.x == 0) ? 0 : sm[threadIdx.x - 1];
}

__global__ void scan_add_kernel(int* __restrict__ out, const int* __restrict__ bsums,
                                const int* __restrict__ cnt, int* __restrict__ work, int n)
{
    int i = blockIdx.x * 1024 + threadIdx.x;
    if (i < n) {
        int incl = out[i] + bsums[blockIdx.x];
        out[i] = incl;
        work[i] = incl - cnt[i];
    }
}

__global__ void scatter_kernel(const int* __restrict__ rows, const int* __restrict__ cols,
                               const float* __restrict__ vals,
                               int* __restrict__ workA, int2* __restrict__ ivA,
                               int* __restrict__ workB, int2* __restrict__ ivB, int nnz)
{
    int i = blockIdx.x * blockDim.x + threadIdx.x;
    if (i >= nnz) return;
    int r = rows[i], c = cols[i];
    int v = __float_as_int(vals[i]);
    int pa = atomicAdd(workA + r, 1);
    ivA[pa] = make_int2(c, v);
    int pb = atomicAdd(workB + c, 1);
    ivB[pb] = make_int2(r, v);
}

// ---------------------------------------------------------------------------
// CSR SpMM, HALF-WARP per row (16 lanes x LDG.128 = 256B fp16 row):
// Predicated full-width batches (no serial tail; dummy slots repeat the last
// edge with v=0 -> L1-hit gathers). Packed FFMA2 accumulation (4x f32x2).
// Per-column accumulation order identical to scalar version (bitwise same).
//   if (out_h)   out_h[row]   = acc_raw    (fp16, scaled domain)
//   if (out_f)   out_f[row]   = acc_raw * 1024
//   if (sum_out) sum_out[row] = sum_base[row] + acc_raw * 1024
// ---------------------------------------------------------------------------
template<int UNROLL>
__global__ __launch_bounds__(256)
void spmm_csr_h_kernel(const int* __restrict__ ptr, const int2* __restrict__ iv,
                       const uint4* __restrict__ xh,
                       float4* __restrict__ out_f, uint4* __restrict__ out_h,
                       const float4* __restrict__ sum_base,
                       float4* __restrict__ sum_out, int n_rows)
{
    int row = blockIdx.x * 16 + (threadIdx.x >> 4);
    if (row >= n_rows) return;
    const int lane = threadIdx.x & 15;   // owns 8 halfs (one uint4)

    int e   = __ldg(ptr + row);
    int deg = __ldg(ptr + row + 1) - e;

    unsigned long long acc0 = 0ull, acc1 = 0ull, acc2 = 0ull, acc3 = 0ull; // 2x +0.f each

    for (int base = 0; base < deg; base += UNROLL) {
        int2  p[UNROLL];
        float v[UNROLL];
        #pragma unroll
        for (int j = 0; j < UNROLL; j++) {
            int idx = base + j;
            int c = (idx < deg) ? idx : (deg - 1);
            p[j] = __ldg(iv + e + c);
            v[j] = (idx < deg) ? __int_as_float(p[j].y) : 0.f;
        }
        uint4 r[UNROLL];
        #pragma unroll
        for (int j = 0; j < UNROLL; j++)
            r[j] = __ldg(xh + (size_t)p[j].x * 16 + lane);
        #pragma unroll
        for (int j = 0; j < UNROLL; j++) {
            unsigned long long v2 = pack2(v[j], v[j]);
            float2 f0 = __half22float2(*reinterpret_cast<__half2*>(&r[j].x));
            float2 f1 = __half22float2(*reinterpret_cast<__half2*>(&r[j].y));
            float2 f2 = __half22float2(*reinterpret_cast<__half2*>(&r[j].z));
            float2 f3 = __half22float2(*reinterpret_cast<__half2*>(&r[j].w));
            ffma2(acc0, v2, pack2(f0.x, f0.y));
            ffma2(acc1, v2, pack2(f1.x, f1.y));
            ffma2(acc2, v2, pack2(f2.x, f2.y));
            ffma2(acc3, v2, pack2(f3.x, f3.y));
        }
    }

    float2 q0 = unpack2(acc0), q1 = unpack2(acc1);
    float2 q2 = unpack2(acc2), q3 = unpack2(acc3);
    float4 a0 = make_float4(q0.x, q0.y, q1.x, q1.y);
    float4 a1 = make_float4(q2.x, q2.y, q3.x, q3.y);

    size_t o = (size_t)row * 16 + lane;      // uint4-granular index (8 halfs)
    if (out_h) {
        uint2 h0 = pack_h4(a0);
        uint2 h1 = pack_h4(a1);
        out_h[o] = make_uint4(h0.x, h0.y, h1.x, h1.y);
    }
    float4 t0 = make_float4(a0.x * H_UNSCALE, a0.y * H_UNSCALE,
                            a0.z * H_UNSCALE, a0.w * H_UNSCALE);
    float4 t1 = make_float4(a1.x * H_UNSCALE, a1.y * H_UNSCALE,
                            a1.z * H_UNSCALE, a1.w * H_UNSCALE);
    if (out_f) {
        out_f[2 * o]     = t0;
        out_f[2 * o + 1] = t1;
    }
    if (sum_out) {
        float4 b0 = __ldg(sum_base + 2 * o);
        float4 b1 = __ldg(sum_base + 2 * o + 1);
        b0.x += t0.x; b0.y += t0.y; b0.z += t0.z; b0.w += t0.w;
        b1.x += t1.x; b1.y += t1.y; b1.z += t1.z; b1.w += t1.w;
        sum_out[2 * o]     = b0;
        sum_out[2 * o + 1] = b1;
    }
}

// ---------------------------------------------------------------------------
// Fused gated dense layer with packed FFMA2:
//   msg = concat(a, a*g) @ W + b ;  msg_h = msg * 2^-10 (fp16);  edge_sum = ebase + msg
// Persistent 148 blocks; W (128KB) + X tile (64 rows, 64KB) in dynamic smem.
// 256 threads = 8 warps x 8 rows; lane owns 4 output columns as 2x f32x2.
// ---------------------------------------------------------------------------
__global__ void gemm_gate_kernel(const float* __restrict__ node_msg,
                                 const uint2* __restrict__ group_h,  // scaled fp16
                                 const float* __restrict__ W,        // [2*DIM][DIM]
                                 const float* __restrict__ bias,     // [DIM]
                                 uint2* __restrict__ msg_h,          // scaled fp16 out
                                 const float* __restrict__ ebase,
                                 float* __restrict__ edge_sum,
                                 int n_groups)
{
    extern __shared__ float sm[];
    float4* Wsv = (float4*)sm;                     // 2*DIM*DIM floats (128 KB)
    float4* Xsv = (float4*)(sm + 2 * DIM * DIM);   // 64 rows * 2*DIM floats (64 KB)

    {
        const float4* Wv = (const float4*)W;
        for (int i = threadIdx.x; i < 2 * DIM * DIM / 4; i += blockDim.x)
            Wsv[i] = Wv[i];
    }

    const int warp = threadIdx.x >> 5;
    const int lane = threadIdx.x & 31;
    const float4 bv = ((const float4*)bias)[lane];
    const unsigned long long b_lo = pack2(bv.x, bv.y);
    const unsigned long long b_hi = pack2(bv.z, bv.w);

    const float4* nm4 = (const float4*)node_msg;
    __syncthreads();

    for (int tile = blockIdx.x * 64; tile < n_groups; tile += gridDim.x * 64) {
        // Stage X = [a ; a*g_true] for 64 rows (g_true = g_scaled * 1024, exact)
        for (int i = threadIdx.x; i < 64 * 32; i += 256) {
            int rr = i >> 5;        // row in tile
            int kq = i & 31;        // float4 idx within DIM
            int row = tile + rr;
            float4 a = make_float4(0.f, 0.f, 0.f, 0.f);
            float4 g = make_float4(0.f, 0.f, 0.f, 0.f);
            if (row < n_groups) {
                a = nm4[(size_t)row * 32 + kq];
                uint2 gr = __ldg(group_h + (size_t)row * 32 + kq);
                g = unpack_h4(gr.x, gr.y);
            }
            Xsv[rr * 64 + kq] = a;
            Xsv[rr * 64 + 32 + kq] =
                make_float4(a.x * g.x * H_UNSCALE, a.y * g.y * H_UNSCALE,
                            a.z * g.z * H_UNSCALE, a.w * g.w * H_UNSCALE);
        }
        __syncthreads();

        unsigned long long acc_lo[8], acc_hi[8];
        #pragma unroll
        for (int r = 0; r < 8; r++) { acc_lo[r] = b_lo; acc_hi[r] = b_hi; }

        const float4* Xr = Xsv + warp * 8 * 64;   // this warp's 8 rows

        #pragma unroll 1
        for (int kq = 0; kq < 64; kq++) {         // each kq covers 4 k values
            float4 xr[8];
            #pragma unroll
            for (int r = 0; r < 8; r++) xr[r] = Xr[r * 64 + kq];

            #pragma unroll
            for (int j = 0; j < 4; j++) {
                float4 w = Wsv[(kq * 4 + j) * 32 + lane];
                unsigned long long w_lo = pack2(w.x, w.y);
                unsigned long long w_hi = pack2(w.z, w.w);
                #pragma unroll
                for (int r = 0; r < 8; r++) {
                    float xs = (j == 0) ? xr[r].x : (j == 1) ? xr[r].y
                             : (j == 2) ? xr[r].z : xr[r].w;
                    unsigned long long x2 = pack2(xs, xs);
                    ffma2(acc_lo[r], x2, w_lo);
                    ffma2(acc_hi[r], x2, w_hi);
                }
            }
        }

        const float4* eb = (const float4*)ebase;
        float4* es = (float4*)edge_sum;
        int r0 = tile + warp * 8;
        #pragma unroll
        for (int r = 0; r < 8; r++) {
            int row = r0 + r;
            if (row < n_groups) {
                float2 lo = unpack2(acc_lo[r]);
                float2 hi = unpack2(acc_hi[r]);
                float4 v = make_float4(lo.x, lo.y, hi.x, hi.y);
                size_t oi = (size_t)row * 32 + lane;
                msg_h[oi] = pack_h4(make_float4(v.x * H_SCALE, v.y * H_SCALE,
                                                v.z * H_SCALE, v.w * H_SCALE));
                float4 e = __ldg(eb + oi);
                e.x += v.x; e.y += v.y; e.z += v.z; e.w += v.w;
                es[oi] = e;
            }
        }
        __syncthreads();
    }
}

// ---------------------------------------------------------------------------
extern "C" void kernel_launch(void* const* d_in, const int* in_sizes, int n_in,
                              void* d_out, int out_size)
{
    const float* group_emb = (const float*)d_in[0];
    const float* user_emb  = (const float*)d_in[1];
    const int*   rows      = (const int*)d_in[2];
    const int*   cols      = (const int*)d_in[3];
    const float* vals      = (const float*)d_in[4];
    const float* Ws        = (const float*)d_in[5];
    const float* bs        = (const float*)d_in[6];

    const int n_groups = in_sizes[0] / DIM;
    const int n_users  = in_sizes[1] / DIM;
    const int nnz      = in_sizes[2];
    const int layers   = in_sizes[6] / DIM;

    float* node_sum = (float*)d_out;                          // [n_users, DIM]
    float* edge_sum = (float*)d_out + (size_t)n_users * DIM;  // [n_groups, DIM]

    float* node_msg;
    __half *userh, *msgh_base;
    int *cntA, *ptrA, *workA, *bsumA, *cntB, *ptrB, *workB, *bsumB;
    int2 *ivA, *ivB;
    cudaGetSymbolAddress((void**)&node_msg, g_node_msg);
    cudaGetSymbolAddress((void**)&userh, g_userh);
    cudaGetSymbolAddress((void**)&msgh_base, g_msgh);
    cudaGetSymbolAddress((void**)&cntA,  g_cntA);
    cudaGetSymbolAddress((void**)&ptrA,  g_ptrA);
    cudaGetSymbolAddress((void**)&workA, g_workA);
    cudaGetSymbolAddress((void**)&bsumA, g_bsumA);
    cudaGetSymbolAddress((void**)&ivA,   g_ivA);
    cudaGetSymbolAddress((void**)&cntB,  g_cntB);
    cudaGetSymbolAddress((void**)&ptrB,  g_ptrB);
    cudaGetSymbolAddress((void**)&workB, g_workB);
    cudaGetSymbolAddress((void**)&bsumB, g_bsumB);
    cudaGetSymbolAddress((void**)&ivB,   g_ivB);

    __half* msgh[3] = { msgh_base,
                        msgh_base + (size_t)MAX_GROUPS * DIM,
                        msgh_base + 2 * (size_t)MAX_GROUPS * DIM };

    // ---- scaled fp16 conversions of the initial embeddings ----
    {
        int n4u = n_users * DIM / 4;
        f32_to_f16_kernel<<<(n4u + 255) / 256, 256>>>((const float4*)user_emb,
                                                      (uint2*)userh, n4u);
        int n4g = n_groups * DIM / 4;
        f32_to_f16_kernel<<<(n4g + 255) / 256, 256>>>((const float4*)group_emb,
                                                      (uint2*)msgh[2], n4g);
    }

    // ---- Build CSR (by group row) and CSC (by user col), in-graph ----
    cudaMemsetAsync(cntA, 0, (size_t)n_groups * sizeof(int), 0);
    cudaMemsetAsync(cntB, 0, (size_t)n_users * sizeof(int), 0);
    hist_kernel<<<(nnz + 255) / 256, 256>>>(rows, cols, cntA, cntB, nnz);

    const int nbA = (n_groups + 1023) / 1024;
    const int nbB = (n_users + 1023) / 1024;
    scan_block_kernel<<<nbA, 1024>>>(cntA, ptrA + 1, bsumA, n_groups);
    scan_small_kernel<<<1, 256>>>(bsumA, nbA);
    scan_add_kernel<<<nbA, 1024>>>(ptrA + 1, bsumA, cntA, workA, n_groups);
    scan_block_kernel<<<nbB, 1024>>>(cntB, ptrB + 1, bsumB, n_users);
    scan_small_kernel<<<1, 256>>>(bsumB, nbB);
    scan_add_kernel<<<nbB, 1024>>>(ptrB + 1, bsumB, cntB, workB, n_users);

    cudaMemsetAsync(ptrA, 0, sizeof(int), 0);
    cudaMemsetAsync(ptrB, 0, sizeof(int), 0);

    scatter_kernel<<<(nnz + 255) / 256, 256>>>(rows, cols, vals, workA, ivA, workB, ivB, nnz);

    // ---- Layers ----
    const int smem_bytes = (2 * DIM * DIM + 64 * 2 * DIM) * sizeof(float);
    cudaFuncSetAttribute(gemm_gate_kernel,
                         cudaFuncAttributeMaxDynamicSharedMemorySize, smem_bytes);

    const int spmmA_blocks = (n_groups + 15) / 16;   // 16 rows per 256-thread block
    const int spmmB_blocks = (n_users + 15) / 16;

    int cur = 2;   // group_cur slot (starts at converted group_emb)
    int nxt = 0;

    for (int i = 0; i < layers; i++) {
        // node_msg = H @ user_h   (scaled fp16 gather, fp32 out) — deg~40 -> UNROLL 8
        spmm_csr_h_kernel<8><<<spmmA_blocks, 256>>>(ptrA, ivA, (const uint4*)userh,
                                                    (float4*)node_msg, nullptr,
                                                    nullptr, nullptr, n_groups);

        // msg_h = fp16(msg * 2^-10); edge_sum = (i==0 ? group_emb : edge_sum) + msg
        const float* ebase = (i == 0) ? group_emb : edge_sum;
        gemm_gate_kernel<<<148, 256, smem_bytes>>>(
            node_msg, (const uint2*)msgh[cur],
            Ws + (size_t)i * 2 * DIM * DIM, bs + (size_t)i * DIM,
            (uint2*)msgh[nxt], ebase, edge_sum, n_groups);

        // user_h = scaled fp16(H^T @ msg) ; node_sum = (i==0 ? user_emb : node_sum) + true
        // deg~10 -> UNROLL 4. Last layer: user_h dead — skip fp16 store.
        const float* nbase = (i == 0) ? user_emb : node_sum;
        uint4* uh_out = (i == layers - 1) ? nullptr : (uint4*)userh;
        spmm_csr_h_kernel<4><<<spmmB_blocks, 256>>>(ptrB, ivB, (const uint4*)msgh[nxt],
                                                    nullptr, uh_out,
                                                    (const float4*)nbase, (float4*)node_sum,
                                                    n_users);

        cur = nxt;
        nxt = (nxt == 0) ? 1 : 0;
    }
}

// round 11
// speedup vs baseline: 1.0932x; 1.0932x over previous
#include <cuda_runtime.h>
#include <cuda_fp16.h>
#include <cstddef>

#define DIM 128
#define MAX_GROUPS 50000
#define MAX_USERS  200000
#define MAX_NNZ    2000000

#define H_SCALE   0.0009765625f   // 2^-10 (exact)
#define H_UNSCALE 1024.0f         // 2^10  (exact)

// ---------------------------------------------------------------------------
// Scratch (device globals; no allocation allowed)
// ---------------------------------------------------------------------------
__device__ float g_node_msg[(size_t)MAX_GROUPS * DIM];
__device__ __half g_userh[(size_t)MAX_USERS * DIM];          // fp16 user operand (scaled 2^-10)
__device__ __half g_msgh[3][(size_t)MAX_GROUPS * DIM];       // fp16 msg slots (scaled 2^-10)

__device__ int  g_cnt[MAX_GROUPS + MAX_USERS];   // cntA | cntB adjacent -> one memset
__device__ int  g_ptrA[MAX_GROUPS + 1];
__device__ int  g_workA[MAX_GROUPS];
__device__ int  g_bsumA[256];
__device__ int2 g_ivA[MAX_NNZ];          // CSR by group row: (user_col, val)

__device__ int  g_ptrB[MAX_USERS + 1];
__device__ int  g_workB[MAX_USERS];
__device__ int  g_bsumB[256];
__device__ int2 g_ivB[MAX_NNZ];          // CSC by user col: (group_row, val)

// ---------------------------------------------------------------------------
// f32x2 packed-math helpers (Blackwell FFMA2 via PTX)
// ---------------------------------------------------------------------------
__device__ __forceinline__ unsigned long long pack2(float lo, float hi)
{
    unsigned long long r;
    asm("mov.b64 %0, {%1, %2};" : "=l"(r) : "f"(lo), "f"(hi));
    return r;
}
__device__ __forceinline__ void ffma2(unsigned long long& d,
                                      unsigned long long a, unsigned long long b)
{
    asm("fma.rn.f32x2 %0, %1, %2, %0;" : "+l"(d) : "l"(a), "l"(b));
}
__device__ __forceinline__ float2 unpack2(unsigned long long v)
{
    float2 r;
    asm("mov.b64 {%0, %1}, %2;" : "=f"(r.x), "=f"(r.y) : "l"(v));
    return r;
}

// unpack 4 halfs -> float4
__device__ __forceinline__ float4 unpack_h4(unsigned lo, unsigned hi)
{
    __half2 h0 = *reinterpret_cast<__half2*>(&lo);
    __half2 h1 = *reinterpret_cast<__half2*>(&hi);
    float2 a = __half22float2(h0);
    float2 b = __half22float2(h1);
    return make_float4(a.x, a.y, b.x, b.y);
}
// pack float4 -> 4 halfs (uint2)
__device__ __forceinline__ uint2 pack_h4(float4 v)
{
    __half2 h0 = __floats2half2_rn(v.x, v.y);
    __half2 h1 = __floats2half2_rn(v.z, v.w);
    uint2 r;
    r.x = *reinterpret_cast<unsigned*>(&h0);
    r.y = *reinterpret_cast<unsigned*>(&h1);
    return r;
}

// ---------------------------------------------------------------------------
// fp32 -> scaled fp16 for BOTH embeddings in one launch
__global__ void f32_to_f16_dual_kernel(const float4* __restrict__ a, uint2* __restrict__ oa, int n4a,
                                       const float4* __restrict__ b, uint2* __restrict__ ob, int n4b)
{
    int i = blockIdx.x * blockDim.x + threadIdx.x;
    if (i < n4a) {
        float4 v = a[i];
        v.x *= H_SCALE; v.y *= H_SCALE; v.z *= H_SCALE; v.w *= H_SCALE;
        oa[i] = pack_h4(v);
    } else if (i < n4a + n4b) {
        int j = i - n4a;
        float4 v = b[j];
        v.x *= H_SCALE; v.y *= H_SCALE; v.z *= H_SCALE; v.w *= H_SCALE;
        ob[j] = pack_h4(v);
    }
}

// ---------------------------------------------------------------------------
// CSR build: histogram -> merged 3-pass exclusive scan (A and B together)
// ---------------------------------------------------------------------------
__global__ void hist_kernel(const int* __restrict__ rows, const int* __restrict__ cols,
                            int* __restrict__ cntA, int* __restrict__ cntB, int nnz)
{
    int i = blockIdx.x * blockDim.x + threadIdx.x;
    if (i < nnz) {
        atomicAdd(cntA + rows[i], 1);
        atomicAdd(cntB + cols[i], 1);
    }
}

// Stage 1: per-1024-block inclusive scan; A occupies blocks [0,nbA), B the rest.
__global__ void scan_block2_kernel(const int* __restrict__ cntA, int* __restrict__ outA,
                                   int* __restrict__ bsumA, int nA, int nbA,
                                   const int* __restrict__ cntB, int* __restrict__ outB,
                                   int* __restrict__ bsumB, int nB)
{
    __shared__ int sm[1024];
    const int* cnt; int* out; int* bsums; int n; int bid;
    if ((int)blockIdx.x < nbA) { cnt = cntA; out = outA; bsums = bsumA; n = nA; bid = blockIdx.x; }
    else                       { cnt = cntB; out = outB; bsums = bsumB; n = nB; bid = blockIdx.x - nbA; }

    int i = bid * 1024 + threadIdx.x;
    int v = (i < n) ? cnt[i] : 0;
    sm[threadIdx.x] = v;
    __syncthreads();
    for (int off = 1; off < 1024; off <<= 1) {
        int t = (threadIdx.x >= off) ? sm[threadIdx.x - off] : 0;
        __syncthreads();
        sm[threadIdx.x] += t;
        __syncthreads();
    }
    if (i < n) out[i] = sm[threadIdx.x];
    if (threadIdx.x == 1023) bsums[bid] = sm[1023];
}

// Stage 2: exclusive scan of block sums; block 0 -> A, block 1 -> B (nb <= 256)
__global__ void scan_small2_kernel(int* __restrict__ bsumA, int nbA,
                                   int* __restrict__ bsumB, int nbB)
{
    __shared__ int sm[256];
    int* bsums = (blockIdx.x == 0) ? bsumA : bsumB;
    int nb     = (blockIdx.x == 0) ? nbA : nbB;
    int v = (threadIdx.x < nb) ? bsums[threadIdx.x] : 0;
    sm[threadIdx.x] = v;
    __syncthreads();
    for (int off = 1; off < 256; off <<= 1) {
        int t = (threadIdx.x >= off) ? sm[threadIdx.x - off] : 0;
        __syncthreads();
        sm[threadIdx.x] += t;
        __syncthreads();
    }
    if (threadIdx.x < nb)
        bsums[threadIdx.x] = (threadIdx.x == 0) ? 0 : sm[threadIdx.x - 1];
}

// Stage 3: add block offsets; out (ptr+1) gets inclusive scan, work gets the
// exclusive start (incl - cnt). Also writes ptr[0] = 0 (kills two memsets).
__global__ void scan_add2_kernel(int* __restrict__ outA, const int* __restrict__ bsumA,
                                 const int* __restrict__ cntA, int* __restrict__ workA,
                                 int nA, int nbA,
                                 int* __restrict__ outB, const int* __restrict__ bsumB,
                                 const int* __restrict__ cntB, int* __restrict__ workB,
                                 int nB,
                                 int* __restrict__ ptrA0, int* __restrict__ ptrB0)
{
    int* out; const int* bsums; const int* cnt; int* work; int n; int bid;
    if ((int)blockIdx.x < nbA) { out = outA; bsums = bsumA; cnt = cntA; work = workA; n = nA; bid = blockIdx.x; }
    else                       { out = outB; bsums = bsumB; cnt = cntB; work = workB; n = nB; bid = blockIdx.x - nbA; }

    int i = bid * 1024 + threadIdx.x;
    if (i < n) {
        int incl = out[i] + bsums[bid];
        out[i] = incl;
        work[i] = incl - cnt[i];
    }
    if (threadIdx.x == 0 && bid == 0) {
        if ((int)blockIdx.x < nbA) *ptrA0 = 0; else *ptrB0 = 0;
    }
}

__global__ void scatter_kernel(const int* __restrict__ rows, const int* __restrict__ cols,
                               const float* __restrict__ vals,
                               int* __restrict__ workA, int2* __restrict__ ivA,
                               int* __restrict__ workB, int2* __restrict__ ivB, int nnz)
{
    int i = blockIdx.x * blockDim.x + threadIdx.x;
    if (i >= nnz) return;
    int r = rows[i], c = cols[i];
    int v = __float_as_int(vals[i]);
    int pa = atomicAdd(workA + r, 1);
    ivA[pa] = make_int2(c, v);
    int pb = atomicAdd(workB + c, 1);
    ivB[pb] = make_int2(r, v);
}

// ---------------------------------------------------------------------------
// CSR SpMM, HALF-WARP per row (16 lanes x LDG.128 = 256B fp16 row):
// unroll-4 main loop + serial tail (R9 known-good form; near L2 roofline).
//   if (out_h)   out_h[row]   = acc_raw    (fp16, scaled domain)
//   if (out_f)   out_f[row]   = acc_raw * 1024
//   if (sum_out) sum_out[row] = sum_base[row] + acc_raw * 1024
// ---------------------------------------------------------------------------
__global__ __launch_bounds__(256)
void spmm_csr_h_kernel(const int* __restrict__ ptr, const int2* __restrict__ iv,
                       const uint4* __restrict__ xh,
                       float4* __restrict__ out_f, uint4* __restrict__ out_h,
                       const float4* __restrict__ sum_base,
                       float4* __restrict__ sum_out, int n_rows)
{
    int row = blockIdx.x * 16 + (threadIdx.x >> 4);
    if (row >= n_rows) return;
    const int lane = threadIdx.x & 15;   // owns 8 halfs (one uint4)

    int e   = __ldg(ptr + row);
    int end = __ldg(ptr + row + 1);

    float4 a0 = make_float4(0.f, 0.f, 0.f, 0.f);
    float4 a1 = make_float4(0.f, 0.f, 0.f, 0.f);

    for (; e + 4 <= end; e += 4) {
        int2 p0 = __ldg(iv + e);
        int2 p1 = __ldg(iv + e + 1);
        int2 p2 = __ldg(iv + e + 2);
        int2 p3 = __ldg(iv + e + 3);
        uint4 r0 = __ldg(xh + (size_t)p0.x * 16 + lane);
        uint4 r1 = __ldg(xh + (size_t)p1.x * 16 + lane);
        uint4 r2 = __ldg(xh + (size_t)p2.x * 16 + lane);
        uint4 r3 = __ldg(xh + (size_t)p3.x * 16 + lane);
        float v0 = __int_as_float(p0.y), v1 = __int_as_float(p1.y);
        float v2 = __int_as_float(p2.y), v3 = __int_as_float(p3.y);
        float4 u;
        u = unpack_h4(r0.x, r0.y);
        a0.x += v0 * u.x; a0.y += v0 * u.y; a0.z += v0 * u.z; a0.w += v0 * u.w;
        u = unpack_h4(r0.z, r0.w);
        a1.x += v0 * u.x; a1.y += v0 * u.y; a1.z += v0 * u.z; a1.w += v0 * u.w;
        u = unpack_h4(r1.x, r1.y);
        a0.x += v1 * u.x; a0.y += v1 * u.y; a0.z += v1 * u.z; a0.w += v1 * u.w;
        u = unpack_h4(r1.z, r1.w);
        a1.x += v1 * u.x; a1.y += v1 * u.y; a1.z += v1 * u.z; a1.w += v1 * u.w;
        u = unpack_h4(r2.x, r2.y);
        a0.x += v2 * u.x; a0.y += v2 * u.y; a0.z += v2 * u.z; a0.w += v2 * u.w;
        u = unpack_h4(r2.z, r2.w);
        a1.x += v2 * u.x; a1.y += v2 * u.y; a1.z += v2 * u.z; a1.w += v2 * u.w;
        u = unpack_h4(r3.x, r3.y);
        a0.x += v3 * u.x; a0.y += v3 * u.y; a0.z += v3 * u.z; a0.w += v3 * u.w;
        u = unpack_h4(r3.z, r3.w);
        a1.x += v3 * u.x; a1.y += v3 * u.y; a1.z += v3 * u.z; a1.w += v3 * u.w;
    }
    for (; e < end; ++e) {
        int2 p = __ldg(iv + e);
        float v = __int_as_float(p.y);
        uint4 r = __ldg(xh + (size_t)p.x * 16 + lane);
        float4 u;
        u = unpack_h4(r.x, r.y);
        a0.x += v * u.x; a0.y += v * u.y; a0.z += v * u.z; a0.w += v * u.w;
        u = unpack_h4(r.z, r.w);
        a1.x += v * u.x; a1.y += v * u.y; a1.z += v * u.z; a1.w += v * u.w;
    }

    size_t o = (size_t)row * 16 + lane;      // uint4-granular index (8 halfs)
    if (out_h) {
        uint2 h0 = pack_h4(a0);
        uint2 h1 = pack_h4(a1);
        out_h[o] = make_uint4(h0.x, h0.y, h1.x, h1.y);
    }
    float4 t0 = make_float4(a0.x * H_UNSCALE, a0.y * H_UNSCALE,
                            a0.z * H_UNSCALE, a0.w * H_UNSCALE);
    float4 t1 = make_float4(a1.x * H_UNSCALE, a1.y * H_UNSCALE,
                            a1.z * H_UNSCALE, a1.w * H_UNSCALE);
    if (out_f) {
        out_f[2 * o]     = t0;
        out_f[2 * o + 1] = t1;
    }
    if (sum_out) {
        float4 b0 = __ldg(sum_base + 2 * o);
        float4 b1 = __ldg(sum_base + 2 * o + 1);
        b0.x += t0.x; b0.y += t0.y; b0.z += t0.z; b0.w += t0.w;
        b1.x += t1.x; b1.y += t1.y; b1.z += t1.z; b1.w += t1.w;
        sum_out[2 * o]     = b0;
        sum_out[2 * o + 1] = b1;
    }
}

// ---------------------------------------------------------------------------
// Fused gated dense layer with packed FFMA2:
//   msg = concat(a, a*g) @ W + b ;  msg_h = msg * 2^-10 (fp16);  edge_sum = ebase + msg
// Persistent 148 blocks; W (128KB) + X tile (64 rows, 64KB) in dynamic smem.
// 256 threads = 8 warps x 8 rows; lane owns 4 output columns as 2x f32x2.
// ---------------------------------------------------------------------------
__global__ void gemm_gate_kernel(const float* __restrict__ node_msg,
                                 const uint2* __restrict__ group_h,  // scaled fp16
                                 const float* __restrict__ W,        // [2*DIM][DIM]
                                 const float* __restrict__ bias,     // [DIM]
                                 uint2* __restrict__ msg_h,          // scaled fp16 out
                                 const float* __restrict__ ebase,
                                 float* __restrict__ edge_sum,
                                 int n_groups)
{
    extern __shared__ float sm[];
    float4* Wsv = (float4*)sm;                     // 2*DIM*DIM floats (128 KB)
    float4* Xsv = (float4*)(sm + 2 * DIM * DIM);   // 64 rows * 2*DIM floats (64 KB)

    {
        const float4* Wv = (const float4*)W;
        for (int i = threadIdx.x; i < 2 * DIM * DIM / 4; i += blockDim.x)
            Wsv[i] = Wv[i];
    }

    const int warp = threadIdx.x >> 5;
    const int lane = threadIdx.x & 31;
    const float4 bv = ((const float4*)bias)[lane];
    const unsigned long long b_lo = pack2(bv.x, bv.y);
    const unsigned long long b_hi = pack2(bv.z, bv.w);

    const float4* nm4 = (const float4*)node_msg;
    __syncthreads();

    for (int tile = blockIdx.x * 64; tile < n_groups; tile += gridDim.x * 64) {
        // Stage X = [a ; a*g_true] for 64 rows (g_true = g_scaled * 1024, exact)
        for (int i = threadIdx.x; i < 64 * 32; i += 256) {
            int rr = i >> 5;        // row in tile
            int kq = i & 31;        // float4 idx within DIM
            int row = tile + rr;
            float4 a = make_float4(0.f, 0.f, 0.f, 0.f);
            float4 g = make_float4(0.f, 0.f, 0.f, 0.f);
            if (row < n_groups) {
                a = nm4[(size_t)row * 32 + kq];
                uint2 gr = __ldg(group_h + (size_t)row * 32 + kq);
                g = unpack_h4(gr.x, gr.y);
            }
            Xsv[rr * 64 + kq] = a;
            Xsv[rr * 64 + 32 + kq] =
                make_float4(a.x * g.x * H_UNSCALE, a.y * g.y * H_UNSCALE,
                            a.z * g.z * H_UNSCALE, a.w * g.w * H_UNSCALE);
        }
        __syncthreads();

        unsigned long long acc_lo[8], acc_hi[8];
        #pragma unroll
        for (int r = 0; r < 8; r++) { acc_lo[r] = b_lo; acc_hi[r] = b_hi; }

        const float4* Xr = Xsv + warp * 8 * 64;   // this warp's 8 rows

        #pragma unroll 1
        for (int kq = 0; kq < 64; kq++) {         // each kq covers 4 k values
            float4 xr[8];
            #pragma unroll
            for (int r = 0; r < 8; r++) xr[r] = Xr[r * 64 + kq];

            #pragma unroll
            for (int j = 0; j < 4; j++) {
                float4 w = Wsv[(kq * 4 + j) * 32 + lane];
                unsigned long long w_lo = pack2(w.x, w.y);
                unsigned long long w_hi = pack2(w.z, w.w);
                #pragma unroll
                for (int r = 0; r < 8; r++) {
                    float xs = (j == 0) ? xr[r].x : (j == 1) ? xr[r].y
                             : (j == 2) ? xr[r].z : xr[r].w;
                    unsigned long long x2 = pack2(xs, xs);
                    ffma2(acc_lo[r], x2, w_lo);
                    ffma2(acc_hi[r], x2, w_hi);
                }
            }
        }

        const float4* eb = (const float4*)ebase;
        float4* es = (float4*)edge_sum;
        int r0 = tile + warp * 8;
        #pragma unroll
        for (int r = 0; r < 8; r++) {
            int row = r0 + r;
            if (row < n_groups) {
                float2 lo = unpack2(acc_lo[r]);
                float2 hi = unpack2(acc_hi[r]);
                float4 v = make_float4(lo.x, lo.y, hi.x, hi.y);
                size_t oi = (size_t)row * 32 + lane;
                msg_h[oi] = pack_h4(make_float4(v.x * H_SCALE, v.y * H_SCALE,
                                                v.z * H_SCALE, v.w * H_SCALE));
                float4 e = __ldg(eb + oi);
                e.x += v.x; e.y += v.y; e.z += v.z; e.w += v.w;
                es[oi] = e;
            }
        }
        __syncthreads();
    }
}

// ---------------------------------------------------------------------------
extern "C" void kernel_launch(void* const* d_in, const int* in_sizes, int n_in,
                              void* d_out, int out_size)
{
    const float* group_emb = (const float*)d_in[0];
    const float* user_emb  = (const float*)d_in[1];
    const int*   rows      = (const int*)d_in[2];
    const int*   cols      = (const int*)d_in[3];
    const float* vals      = (const float*)d_in[4];
    const float* Ws        = (const float*)d_in[5];
    const float* bs        = (const float*)d_in[6];

    const int n_groups = in_sizes[0] / DIM;
    const int n_users  = in_sizes[1] / DIM;
    const int nnz      = in_sizes[2];
    const int layers   = in_sizes[6] / DIM;

    float* node_sum = (float*)d_out;                          // [n_users, DIM]
    float* edge_sum = (float*)d_out + (size_t)n_users * DIM;  // [n_groups, DIM]

    float* node_msg;
    __half *userh, *msgh_base;
    int *cnt, *ptrA, *workA, *bsumA, *ptrB, *workB, *bsumB;
    int2 *ivA, *ivB;
    cudaGetSymbolAddress((void**)&node_msg, g_node_msg);
    cudaGetSymbolAddress((void**)&userh, g_userh);
    cudaGetSymbolAddress((void**)&msgh_base, g_msgh);
    cudaGetSymbolAddress((void**)&cnt,   g_cnt);
    cudaGetSymbolAddress((void**)&ptrA,  g_ptrA);
    cudaGetSymbolAddress((void**)&workA, g_workA);
    cudaGetSymbolAddress((void**)&bsumA, g_bsumA);
    cudaGetSymbolAddress((void**)&ivA,   g_ivA);
    cudaGetSymbolAddress((void**)&ptrB,  g_ptrB);
    cudaGetSymbolAddress((void**)&workB, g_workB);
    cudaGetSymbolAddress((void**)&bsumB, g_bsumB);
    cudaGetSymbolAddress((void**)&ivB,   g_ivB);

    int* cntA = cnt;
    int* cntB = cnt + MAX_GROUPS;

    __half* msgh[3] = { msgh_base,
                        msgh_base + (size_t)MAX_GROUPS * DIM,
                        msgh_base + 2 * (size_t)MAX_GROUPS * DIM };

    // ---- scaled fp16 conversions of both embeddings (one launch) ----
    {
        int n4u = n_users * DIM / 4;
        int n4g = n_groups * DIM / 4;
        int n4 = n4u + n4g;
        f32_to_f16_dual_kernel<<<(n4 + 255) / 256, 256>>>(
            (const float4*)user_emb, (uint2*)userh, n4u,
            (const float4*)group_emb, (uint2*)msgh[2], n4g);
    }

    // ---- Build CSR (by group row) and CSC (by user col), in-graph ----
    cudaMemsetAsync(cnt, 0, ((size_t)MAX_GROUPS + n_users) * sizeof(int), 0);
    hist_kernel<<<(nnz + 255) / 256, 256>>>(rows, cols, cntA, cntB, nnz);

    const int nbA = (n_groups + 1023) / 1024;
    const int nbB = (n_users + 1023) / 1024;
    scan_block2_kernel<<<nbA + nbB, 1024>>>(cntA, ptrA + 1, bsumA, n_groups, nbA,
                                            cntB, ptrB + 1, bsumB, n_users);
    scan_small2_kernel<<<2, 256>>>(bsumA, nbA, bsumB, nbB);
    scan_add2_kernel<<<nbA + nbB, 1024>>>(ptrA + 1, bsumA, cntA, workA, n_groups, nbA,
                                          ptrB + 1, bsumB, cntB, workB, n_users,
                                          ptrA, ptrB);

    scatter_kernel<<<(nnz + 255) / 256, 256>>>(rows, cols, vals, workA, ivA, workB, ivB, nnz);

    // ---- Layers ----
    const int smem_bytes = (2 * DIM * DIM + 64 * 2 * DIM) * sizeof(float);
    cudaFuncSetAttribute(gemm_gate_kernel,
                         cudaFuncAttributeMaxDynamicSharedMemorySize, smem_bytes);

    const int spmmA_blocks = (n_groups + 15) / 16;   // 16 rows per 256-thread block
    const int spmmB_blocks = (n_users + 15) / 16;

    int cur = 2;   // group_cur slot (starts at converted group_emb)
    int nxt = 0;

    for (int i = 0; i < layers; i++) {
        // node_msg = H @ user_h   (scaled fp16 gather, fp32 out)
        spmm_csr_h_kernel<<<spmmA_blocks, 256>>>(ptrA, ivA, (const uint4*)userh,
                                                 (float4*)node_msg, nullptr,
                                                 nullptr, nullptr, n_groups);

        // msg_h = fp16(msg * 2^-10); edge_sum = (i==0 ? group_emb : edge_sum) + msg
        const float* ebase = (i == 0) ? group_emb : edge_sum;
        gemm_gate_kernel<<<148, 256, smem_bytes>>>(
            node_msg, (const uint2*)msgh[cur],
            Ws + (size_t)i * 2 * DIM * DIM, bs + (size_t)i * DIM,
            (uint2*)msgh[nxt], ebase, edge_sum, n_groups);

        // user_h = scaled fp16(H^T @ msg) ; node_sum = (i==0 ? user_emb : node_sum) + true
        // Last layer: user_h dead — skip fp16 store.
        const float* nbase = (i == 0) ? user_emb : node_sum;
        uint4* uh_out = (i == layers - 1) ? nullptr : (uint4*)userh;
        spmm_csr_h_kernel<<<spmmB_blocks, 256>>>(ptrB, ivB, (const uint4*)msgh[nxt],
                                                 nullptr, uh_out,
                                                 (const float4*)nbase, (float4*)node_sum,
                                                 n_users);

        cur = nxt;
        nxt = (nxt == 0) ? 1 : 0;
    }
}